// round 1
// baseline (speedup 1.0000x reference)
#include <cuda_runtime.h>
#include <stdint.h>

// Problem constants
#define IMGS 128          // 8 * 16 images
#define H 512
#define W 512
#define BINS 256          // 16 x 16 joint GLCM
#define SLABS 8           // row-slabs per image
#define RPS (H / SLABS)   // 64 rows per CTA
#define TPB 128           // threads per hist CTA; 4 pixels per thread
#define NWARP (TPB / 32)  // 4 per-warp histogram copies

// Global accumulation buffer (allocation-free scratch).
__device__ unsigned int g_counts[IMGS * BINS];

// ---------------------------------------------------------------------------
// Kernel 0: zero the global count buffer (graph replays re-run this).
// ---------------------------------------------------------------------------
__global__ void zero_counts_k() {
    int i = blockIdx.x * blockDim.x + threadIdx.x;
    if (i < IMGS * BINS) g_counts[i] = 0u;
}

// ---------------------------------------------------------------------------
// Kernel 1: per-slab GLCM histogram with per-warp privatized smem bins.
// Grid: (SLABS, IMGS), Block: TPB threads, 4 columns per thread.
// Pairs per pixel (i,j), matching jnp.roll semantics:
//   s0 = q[i, j-1], s1 = q[i-1, j+1], s2 = q[i-1, j], s3 = q[i-1, j-1]
// (all indices wrapped mod 512).
// ---------------------------------------------------------------------------
__global__ __launch_bounds__(TPB) void glcm_hist_k(const float* __restrict__ x) {
    __shared__ unsigned int hist[NWARP][BINS];
    __shared__ unsigned char qbuf[2][W];   // double-buffered quantized rows

    const int t    = threadIdx.x;
    const int wid  = t >> 5;
    const int img  = blockIdx.y;
    const int slab = blockIdx.x;
    const int j0   = t * 4;
    const float* __restrict__ base = x + (size_t)img * (H * W);

    // zero private histograms
    #pragma unroll
    for (int i = t; i < NWARP * BINS; i += TPB)
        (&hist[0][0])[i] = 0u;

    const int r0 = slab * RPS;   // even (RPS = 64)

    // Preload wrapped previous row (r0-1 mod H) into qbuf[1].
    {
        const int ip = (r0 + H - 1) & (H - 1);
        float4 v = *(const float4*)(base + (size_t)ip * W + j0);
        unsigned q0 = (unsigned)(int)(v.x * 15.0f);   // FMUL + trunc: bit-exact vs ref
        unsigned q1 = (unsigned)(int)(v.y * 15.0f);
        unsigned q2 = (unsigned)(int)(v.z * 15.0f);
        unsigned q3 = (unsigned)(int)(v.w * 15.0f);
        *(unsigned*)&qbuf[1][j0] = q0 | (q1 << 8) | (q2 << 16) | (q3 << 24);
    }
    __syncthreads();

    unsigned int* hrow = hist[wid];

    for (int r = 0; r < RPS; r++) {
        const int i   = r0 + r;
        const int cur = i & 1;        // row content of row i lives in qbuf[i & 1]
        const int prv = cur ^ 1;

        float4 v = *(const float4*)(base + (size_t)i * W + j0);
        int q0 = (int)(v.x * 15.0f);
        int q1 = (int)(v.y * 15.0f);
        int q2 = (int)(v.z * 15.0f);
        int q3 = (int)(v.w * 15.0f);
        *(unsigned*)&qbuf[cur][j0] =
            (unsigned)q0 | ((unsigned)q1 << 8) | ((unsigned)q2 << 16) | ((unsigned)q3 << 24);
        __syncthreads();   // cur row complete before neighbor reads

        // Neighbor window reads (minimal LDS count):
        const unsigned pm1 = qbuf[prv][(j0 + W - 1) & (W - 1)];   // prev[j0-1]
        const unsigned pw  = *(const unsigned*)&qbuf[prv][j0];    // prev[j0..j0+3]
        const unsigned pp4 = qbuf[prv][(j0 + 4) & (W - 1)];       // prev[j0+4]
        const unsigned cm1 = qbuf[cur][(j0 + W - 1) & (W - 1)];   // cur[j0-1]

        const unsigned p0 =  pw        & 0xffu;
        const unsigned p1 = (pw >> 8)  & 0xffu;
        const unsigned p2 = (pw >> 16) & 0xffu;
        const unsigned p3 =  pw >> 24;

        // pixel j0:   center q0, s = {cm1, p1, p0, pm1}
        {
            const unsigned b = (unsigned)q0 << 4;
            atomicAdd(&hrow[b + cm1], 1u);
            atomicAdd(&hrow[b + p1 ], 1u);
            atomicAdd(&hrow[b + p0 ], 1u);
            atomicAdd(&hrow[b + pm1], 1u);
        }
        // pixel j0+1: center q1, s = {q0, p2, p1, p0}
        {
            const unsigned b = (unsigned)q1 << 4;
            atomicAdd(&hrow[b + (unsigned)q0], 1u);
            atomicAdd(&hrow[b + p2], 1u);
            atomicAdd(&hrow[b + p1], 1u);
            atomicAdd(&hrow[b + p0], 1u);
        }
        // pixel j0+2: center q2, s = {q1, p3, p2, p1}
        {
            const unsigned b = (unsigned)q2 << 4;
            atomicAdd(&hrow[b + (unsigned)q1], 1u);
            atomicAdd(&hrow[b + p3], 1u);
            atomicAdd(&hrow[b + p2], 1u);
            atomicAdd(&hrow[b + p1], 1u);
        }
        // pixel j0+3: center q3, s = {q2, pp4, p3, p2}
        {
            const unsigned b = (unsigned)q3 << 4;
            atomicAdd(&hrow[b + (unsigned)q2], 1u);
            atomicAdd(&hrow[b + pp4], 1u);
            atomicAdd(&hrow[b + p3 ], 1u);
            atomicAdd(&hrow[b + p2 ], 1u);
        }
        __syncthreads();   // prv buffer consumed before next iteration overwrites it
    }

    // Flush: sum the warp copies, accumulate into the per-image global bins.
    for (int b = t; b < BINS; b += TPB) {
        unsigned s = 0u;
        #pragma unroll
        for (int wI = 0; wI < NWARP; wI++) s += hist[wI][b];
        atomicAdd(&g_counts[img * BINS + b], s);
    }
}

// ---------------------------------------------------------------------------
// Kernel 2: entropy per image + broadcast write. 4 CTAs per image.
// ---------------------------------------------------------------------------
__global__ __launch_bounds__(256) void entropy_bcast_k(float* __restrict__ out) {
    const int img  = blockIdx.x >> 2;
    const int part = blockIdx.x & 3;
    const int t    = threadIdx.x;

    __shared__ float red[256];
    const float c = (float)g_counts[img * BINS + t];
    const float p = c * (1.0f / (4.0f * H * W));     // total is always 4*H*W
    red[t] = -p * logf(p + 1e-10f);                  // matches -sum(g*log(g+1e-10))
    __syncthreads();
    #pragma unroll
    for (int s = 128; s > 0; s >>= 1) {
        if (t < s) red[t] += red[t + s];
        __syncthreads();
    }
    const float e = red[0];

    const float4 val = make_float4(e, e, e, e);
    float4* o = (float4*)(out + (size_t)img * (H * W) + (size_t)part * (H * W / 4));
    #pragma unroll 4
    for (int k = t; k < (H * W / 4) / 4; k += 256)   // 16384 float4 per part
        o[k] = val;
}

// ---------------------------------------------------------------------------
// Launch: zero -> histogram -> entropy+broadcast (all graph-capturable).
// ---------------------------------------------------------------------------
extern "C" void kernel_launch(void* const* d_in, const int* in_sizes, int n_in,
                              void* d_out, int out_size) {
    const float* x = (const float*)d_in[0];
    float* out = (float*)d_out;
    (void)in_sizes; (void)n_in; (void)out_size;

    zero_counts_k<<<(IMGS * BINS + 255) / 256, 256>>>();
    dim3 g(SLABS, IMGS);
    glcm_hist_k<<<g, TPB>>>(x);
    entropy_bcast_k<<<IMGS * 4, 256>>>(out);
}